// round 16
// baseline (speedup 1.0000x reference)
#include <cuda_runtime.h>
#include <cuda_fp16.h>
#include <math.h>
#include <stdint.h>

typedef long long LL;
typedef __half fp16;

#define BATCH   16
#define SEQ     197
#define SEQP    256
#define NPATCH  196
#define DIM     768
#define NH      12
#define HDK     9216
#define HDK3    27648
#define MLP     3072
#define ROWS    (BATCH*SEQ)     /* 3152 */
#define PROWS   (BATCH*NPATCH)  /* 3136 */
#define NLAYER  4
#define NC      4
#define NBH     (BATCH*NH)      /* 192 */

// ---------------- scratch (device globals) ----------------
__device__ float g_PO [PROWS*DIM];
__device__ float g_H  [ROWS*DIM];
__device__ float g_BfL[(LL)NLAYER*HDK3];
__device__ float g_Part[(LL)24*HDK3];
__device__ float g_S  [(LL)NBH*SEQ*SEQP];

__device__ fp16 g_Xn  [ROWS*DIM];
__device__ fp16 g_Xp  [PROWS*DIM];
__device__ fp16 g_QKV [(LL)ROWS*HDK3];
__device__ fp16 g_Cat [(LL)ROWS*HDK];
__device__ fp16 g_Hid [(LL)ROWS*MLP];
__device__ fp16 g_Ph  [(LL)NBH*SEQ*SEQP];
__device__ fp16 g_WqkvL[(LL)NLAYER*3*HDK*DIM];
__device__ fp16 g_WoL [(LL)NLAYER*HDK*DIM];
__device__ fp16 g_W1L [(LL)NLAYER*DIM*MLP];
__device__ fp16 g_W2L [(LL)NLAYER*MLP*DIM];
__device__ fp16 g_Wp  [DIM*DIM];

// ---------------- helpers ----------------
__device__ __forceinline__ uint32_t smem_u32(const void* p) {
    uint32_t a;
    asm("{ .reg .u64 t; cvta.to.shared.u64 t, %1; cvt.u32.u64 %0, t; }" : "=r"(a) : "l"(p));
    return a;
}
__device__ __forceinline__ uint32_t swz(uint32_t off) { return off ^ ((off >> 3) & 0x70); }

__device__ __forceinline__ void cp16z(uint32_t dst, const void* src, uint32_t sz) {
    asm volatile("cp.async.cg.shared.global [%0], [%1], 16, %2;\n"
                 :: "r"(dst), "l"(src), "r"(sz) : "memory");
}
__device__ __forceinline__ void cp_commit() {
    asm volatile("cp.async.commit_group;\n" ::: "memory");
}
__device__ __forceinline__ void ldsm4(uint32_t* r, uint32_t addr) {
    asm volatile("ldmatrix.sync.aligned.m8n8.x4.shared.b16 {%0,%1,%2,%3}, [%4];\n"
                 : "=r"(r[0]), "=r"(r[1]), "=r"(r[2]), "=r"(r[3]) : "r"(addr));
}
__device__ __forceinline__ void ldsm4t(uint32_t* r, uint32_t addr) {
    asm volatile("ldmatrix.sync.aligned.m8n8.x4.trans.shared.b16 {%0,%1,%2,%3}, [%4];\n"
                 : "=r"(r[0]), "=r"(r[1]), "=r"(r[2]), "=r"(r[3]) : "r"(addr));
}
__device__ __forceinline__ void mma16816(float* c, const uint32_t* a, const uint32_t* b) {
    asm volatile(
        "mma.sync.aligned.m16n8k16.row.col.f32.f16.f16.f32 "
        "{%0,%1,%2,%3}, {%4,%5,%6,%7}, {%8,%9}, {%0,%1,%2,%3};\n"
        : "+f"(c[0]), "+f"(c[1]), "+f"(c[2]), "+f"(c[3])
        : "r"(a[0]), "r"(a[1]), "r"(a[2]), "r"(a[3]), "r"(b[0]), "r"(b[1]));
}

#define EPI_BIAS   1
#define EPI_RES    2
#define EPI_GELU   4
#define EPI_SPLITH 16

// ================= mm1: 512 thr, BM=128 x BN=256, 4-stage ===================
#define MM_SMEM 196608

__device__ __forceinline__ void load_tile1(uint32_t stg,
    const fp16* __restrict__ A, const fp16* __restrict__ B,
    int bm, int bn, int M, int Brows, int lda, int ldb, int k0, int tid)
{
    constexpr uint32_t SB = 16384;
    #pragma unroll
    for (int it = 0; it < 2; it++) {
        int i = tid + it*512;
        int row = i >> 3, j = i & 7;
        int gm = bm + row;
        uint32_t sz = (gm < M) ? 16u : 0u;
        int gmc = (gm < M) ? gm : 0;
        const char* p = (const char*)(A + (LL)gmc*lda + k0) + j*16;
        cp16z(stg + swz((uint32_t)row*128u + (uint32_t)j*16u), p, sz);
    }
    #pragma unroll
    for (int it = 0; it < 4; it++) {
        int i = tid + it*512;
        int row = i >> 3, j = i & 7;
        int gn = bn + row;
        uint32_t sz = (gn < Brows) ? 16u : 0u;
        int gnc = (gn < Brows) ? gn : 0;
        const char* p = (const char*)(B + (LL)gnc*ldb + k0) + j*16;
        cp16z(stg + SB + swz((uint32_t)row*128u + (uint32_t)j*16u), p, sz);
    }
}

template<int EPI>
__global__ void __launch_bounds__(512, 1)
mm1(const fp16* __restrict__ A, const fp16* __restrict__ B,
    float* __restrict__ C, fp16* __restrict__ Ch,
    const float* __restrict__ bias, const float* __restrict__ res,
    int M, int N, int Brows, int K, int lda, int ldb, int ldc, float alpha)
{
    constexpr uint32_t SB = 16384;
    constexpr int STG = 49152, NSTG = 4;

    extern __shared__ char smem[];
    uint32_t sb = smem_u32(smem);
    const int tid  = threadIdx.x;
    const int wid  = tid >> 5;
    const int lane = tid & 31;
    const int bm = blockIdx.y * 128;
    const int bn = blockIdx.x * 256;

    const int m_warp = (wid & 3) * 32;
    const int n_warp = (wid >> 2) * 64;

    float acc[2][8][4];
    #pragma unroll
    for (int mt = 0; mt < 2; mt++)
        #pragma unroll
        for (int nt = 0; nt < 8; nt++)
            #pragma unroll
            for (int e = 0; e < 4; e++) acc[mt][nt][e] = 0.f;

    const int NCH = K >> 6;

    #pragma unroll
    for (int s = 0; s < NSTG-1; s++) {
        if (s < NCH)
            load_tile1(sb + s*STG, A, B, bm, bn, M, Brows, lda, ldb, s*64, tid);
        cp_commit();
    }

    const int lar = lane & 15;
    const int lac = (lane >> 4) * 16;
    const int lbr = ((lane & 16) >> 1) + (lane & 7);
    const int lbc = ((lane >> 3) & 1) * 16;

    for (int c = 0; c < NCH; c++) {
        if (c + NSTG-1 < NCH)
            load_tile1(sb + ((c + NSTG-1) % NSTG)*STG,
                       A, B, bm, bn, M, Brows, lda, ldb, (c + NSTG-1)*64, tid);
        cp_commit();
        asm volatile("cp.async.wait_group %0;\n" :: "n"(NSTG-1) : "memory");
        __syncthreads();

        uint32_t stg = sb + (c % NSTG)*STG;
        #pragma unroll
        for (int ks = 0; ks < 4; ks++) {
            uint32_t a[2][4];
            #pragma unroll
            for (int mt = 0; mt < 2; mt++) {
                uint32_t off = swz((uint32_t)(m_warp + mt*16 + lar)*128u + ks*32 + lac);
                ldsm4(a[mt], stg + off);
            }
            #pragma unroll
            for (int p = 0; p < 4; p++) {
                uint32_t rb[4];
                uint32_t off = swz((uint32_t)(n_warp + p*16 + lbr)*128u + ks*32 + lbc);
                ldsm4(rb, stg + SB + off);
                #pragma unroll
                for (int mt = 0; mt < 2; mt++) {
                    mma16816(acc[mt][2*p],   a[mt], rb);
                    mma16816(acc[mt][2*p+1], a[mt], rb+2);
                }
            }
        }
        __syncthreads();
    }

    #pragma unroll
    for (int mt = 0; mt < 2; mt++) {
        #pragma unroll
        for (int half = 0; half < 2; half++) {
            int m = bm + m_warp + mt*16 + (lane >> 2) + half*8;
            if (m >= M) continue;
            #pragma unroll
            for (int nt = 0; nt < 8; nt++) {
                int n = bn + n_warp + nt*8 + (lane & 3)*2;
                if (n >= N) continue;
                float v0 = acc[mt][nt][half*2 + 0] * alpha;
                float v1 = acc[mt][nt][half*2 + 1] * alpha;
                if (EPI & EPI_BIAS) { v0 += __ldg(&bias[n]); v1 += __ldg(&bias[n+1]); }
                if (EPI & EPI_RES) {
                    const float2 rv = *(const float2*)(res + (LL)m*ldc + n);
                    v0 += rv.x; v1 += rv.y;
                }
                if (EPI & EPI_GELU) {
                    v0 = 0.5f*v0*(1.f + erff(v0*0.70710678118654752440f));
                    v1 = 0.5f*v1*(1.f + erff(v1*0.70710678118654752440f));
                }
                if (EPI & EPI_SPLITH) {
                    __half2 ph; ph.x = __float2half_rn(v0); ph.y = __float2half_rn(v1);
                    *(__half2*)(Ch + (LL)m*ldc + n) = ph;
                } else {
                    *(float2*)(C + (LL)m*ldc + n) = make_float2(v0, v1);
                }
            }
        }
    }
}

// ================= mms: 256 thr, BM=64 x BN=128, 3-stage, 3 CTA/SM ==========
#define MS_SMEM 73728

template<bool BT>
__device__ __forceinline__ void load_tile_s(uint32_t stg,
    const fp16* __restrict__ A, const fp16* __restrict__ B,
    int bm, int bn, int M, int Brows, int lda, int ldb, int k0, int tid)
{
    constexpr uint32_t SB = 8192;
    #pragma unroll
    for (int it = 0; it < 2; it++) {
        int i = tid + it*256;
        int row = i >> 3, j = i & 7;
        int gm = bm + row;
        uint32_t sz = (gm < M) ? 16u : 0u;
        int gmc = (gm < M) ? gm : 0;
        const char* p = (const char*)(A + (LL)gmc*lda + k0) + j*16;
        cp16z(stg + swz((uint32_t)row*128u + (uint32_t)j*16u), p, sz);
    }
    if (!BT) {
        #pragma unroll
        for (int it = 0; it < 4; it++) {
            int i = tid + it*256;
            int row = i >> 3, j = i & 7;
            int gn = bn + row;
            uint32_t sz = (gn < Brows) ? 16u : 0u;
            int gnc = (gn < Brows) ? gn : 0;
            const char* p = (const char*)(B + (LL)gnc*ldb + k0) + j*16;
            cp16z(stg + SB + swz((uint32_t)row*128u + (uint32_t)j*16u), p, sz);
        }
    } else {
        #pragma unroll
        for (int it = 0; it < 4; it++) {
            int i = tid + it*256;
            int row = i >> 4, j = i & 15;
            int gk = k0 + row;
            uint32_t sz = (gk < Brows) ? 16u : 0u;
            int gkc = (gk < Brows) ? gk : 0;
            const char* p = (const char*)(B + (LL)gkc*ldb + bn) + j*16;
            uint32_t so = (uint32_t)row*256u + (((uint32_t)j*16u) ^ (((uint32_t)row & 7u) << 4));
            cp16z(stg + SB + so, p, sz);
        }
    }
}

template<int EPI, bool BT>
__global__ void __launch_bounds__(256, 3)
mms(const fp16* __restrict__ A, const fp16* __restrict__ B,
    float* __restrict__ C, fp16* __restrict__ Ch,
    const float* __restrict__ bias, const float* __restrict__ res,
    int M, int N, int Brows, int K, int lda, int ldb, int ldc,
    int zdiv, LL sA0, LL sA1, LL sB0, LL sB1, LL sC0, LL sC1,
    float alpha)
{
    constexpr uint32_t SB = 8192;
    constexpr int STG = 24576, NSTG = 3;

    extern __shared__ char smem[];
    uint32_t sb = smem_u32(smem);
    const int tid  = threadIdx.x;
    const int wid  = tid >> 5;
    const int lane = tid & 31;
    const int bm = blockIdx.y * 64;
    const int bn = blockIdx.x * 128;
    const int zo = blockIdx.z / zdiv, zi = blockIdx.z - zo*zdiv;
    A += zo*sA0 + zi*sA1;
    B += zo*sB0 + zi*sB1;
    const LL cbase = zo*sC0 + zi*sC1;

    const int m_warp = (wid & 1) * 32;
    const int n_warp = (wid >> 1) * 32;

    float acc[2][4][4];
    #pragma unroll
    for (int mt = 0; mt < 2; mt++)
        #pragma unroll
        for (int nt = 0; nt < 4; nt++)
            #pragma unroll
            for (int e = 0; e < 4; e++) acc[mt][nt][e] = 0.f;

    const int NCH = K >> 6;

    #pragma unroll
    for (int s = 0; s < NSTG-1; s++) {
        if (s < NCH)
            load_tile_s<BT>(sb + s*STG, A, B, bm, bn, M, Brows, lda, ldb, s*64, tid);
        cp_commit();
    }

    const int lar = lane & 15;
    const int lac = (lane >> 4) * 16;
    const int lbr = ((lane & 16) >> 1) + (lane & 7);
    const int lbc = ((lane >> 3) & 1) * 16;

    for (int c = 0; c < NCH; c++) {
        if (c + NSTG-1 < NCH)
            load_tile_s<BT>(sb + ((c + NSTG-1) % NSTG)*STG,
                            A, B, bm, bn, M, Brows, lda, ldb, (c + NSTG-1)*64, tid);
        cp_commit();
        asm volatile("cp.async.wait_group %0;\n" :: "n"(NSTG-1) : "memory");
        __syncthreads();

        uint32_t stg = sb + (c % NSTG)*STG;
        #pragma unroll
        for (int ks = 0; ks < 4; ks++) {
            uint32_t a[2][4];
            #pragma unroll
            for (int mt = 0; mt < 2; mt++) {
                uint32_t off = swz((uint32_t)(m_warp + mt*16 + lar)*128u + ks*32 + lac);
                ldsm4(a[mt], stg + off);
            }
            #pragma unroll
            for (int p = 0; p < 2; p++) {
                uint32_t rb[4];
                if (!BT) {
                    uint32_t off = swz((uint32_t)(n_warp + p*16 + lbr)*128u + ks*32 + lbc);
                    ldsm4(rb, stg + SB + off);
                } else {
                    uint32_t row = (uint32_t)(ks*16 + (lane & 15));
                    uint32_t nb  = (uint32_t)((n_warp + p*16)*2) + (((uint32_t)lane >> 4) << 4);
                    uint32_t off = row*256u + (nb ^ ((row & 7u) << 4));
                    ldsm4t(rb, stg + SB + off);
                }
                #pragma unroll
                for (int mt = 0; mt < 2; mt++) {
                    mma16816(acc[mt][2*p],   a[mt], rb);
                    mma16816(acc[mt][2*p+1], a[mt], rb+2);
                }
            }
        }
        __syncthreads();
    }

    #pragma unroll
    for (int mt = 0; mt < 2; mt++) {
        #pragma unroll
        for (int half = 0; half < 2; half++) {
            int m = bm + m_warp + mt*16 + (lane >> 2) + half*8;
            if (m >= M) continue;
            #pragma unroll
            for (int nt = 0; nt < 4; nt++) {
                int n = bn + n_warp + nt*8 + (lane & 3)*2;
                if (n >= N) continue;
                float v0 = acc[mt][nt][half*2 + 0] * alpha;
                float v1 = acc[mt][nt][half*2 + 1] * alpha;
                if (EPI & EPI_BIAS) { v0 += __ldg(&bias[n]); v1 += __ldg(&bias[n+1]); }
                if (EPI & EPI_RES) {
                    const float2 rv = *(const float2*)(res + (LL)m*ldc + n);
                    v0 += rv.x; v1 += rv.y;
                }
                if (EPI & EPI_GELU) {
                    v0 = 0.5f*v0*(1.f + erff(v0*0.70710678118654752440f));
                    v1 = 0.5f*v1*(1.f + erff(v1*0.70710678118654752440f));
                }
                if (EPI & EPI_SPLITH) {
                    __half2 ph; ph.x = __float2half_rn(v0); ph.y = __float2half_rn(v1);
                    *(__half2*)(Ch + cbase + (LL)m*ldc + n) = ph;
                } else {
                    *(float2*)(C + cbase + (LL)m*ldc + n) = make_float2(v0, v1);
                }
            }
        }
    }
}

// ---------------- conversion / small kernels ----------------
__global__ void conv_k(const float4* __restrict__ in, fp16* __restrict__ out, int n4) {
    int i = blockIdx.x*blockDim.x + threadIdx.x;
    if (i >= n4) return;
    float4 v = in[i];
    __half2 a, b;
    a.x = __float2half_rn(v.x); a.y = __float2half_rn(v.y);
    b.x = __float2half_rn(v.z); b.y = __float2half_rn(v.w);
    *(__half2*)(out + i*4)     = a;
    *(__half2*)(out + i*4 + 2) = b;
}

__global__ void fold_qkv_w(const float* __restrict__ Wq, const float* __restrict__ Wk,
                           const float* __restrict__ Wv, const float* __restrict__ g,
                           const float* __restrict__ b1,
                           fp16* __restrict__ out, float* __restrict__ part) {
    __shared__ float t[32][33];
    __shared__ float red[8][32];
    int z = blockIdx.z;
    int m = z / NH, h = z % NH;
    const float* W = ((m == 0) ? Wq : (m == 1) ? Wk : Wv) + (LL)h*DIM*DIM;
    int d0 = blockIdx.y*32, k0 = blockIdx.x*32;
    const float* b1h = b1 + (LL)h*DIM;
    float pb = 0.f;
    for (int i = threadIdx.y; i < 32; i += 8) {
        float w = W[(LL)(d0+i)*DIM + k0 + threadIdx.x];
        t[i][threadIdx.x] = w * g[h*DIM + d0 + i];
        pb = fmaf(b1h[d0 + i], w, pb);
    }
    red[threadIdx.y][threadIdx.x] = pb;
    __syncthreads();
    for (int i = threadIdx.y; i < 32; i += 8)
        out[(LL)(m*HDK + h*DIM + k0 + i)*DIM + d0 + threadIdx.x] = __float2half_rn(t[threadIdx.x][i]);
    if (threadIdx.y == 0) {
        float s = red[0][threadIdx.x];
        #pragma unroll
        for (int j = 1; j < 8; j++) s += red[j][threadIdx.x];
        part[(LL)blockIdx.y*HDK3 + m*HDK + h*DIM + k0 + threadIdx.x] = s;
    }
}

__global__ void reduce_bf(const float* __restrict__ part,
                          const float* __restrict__ bq, const float* __restrict__ bk,
                          const float* __restrict__ bv, float* __restrict__ Bf) {
    int n = blockIdx.x*256 + threadIdx.x;
    if (n >= HDK3) return;
    int m = n / HDK, r = n - m*HDK;
    float s = ((m == 0) ? bq : (m == 1) ? bk : bv)[r];
    #pragma unroll 8
    for (int j = 0; j < 24; j++) s += part[(LL)j*HDK3 + n];
    Bf[n] = s;
}

__global__ void tconv_k(const float* __restrict__ W, fp16* __restrict__ out, int K, int N) {
    __shared__ float t[32][33];
    int k0 = blockIdx.x*32, n0 = blockIdx.y*32;
    for (int i = threadIdx.y; i < 32; i += 8)
        t[i][threadIdx.x] = W[(LL)(k0+i)*N + n0 + threadIdx.x];
    __syncthreads();
    for (int i = threadIdx.y; i < 32; i += 8)
        out[(LL)(n0+i)*K + k0 + threadIdx.x] = __float2half_rn(t[threadIdx.x][i]);
}

__global__ void im2col_half(const float* __restrict__ x, fp16* __restrict__ oh) {
    int idx = blockIdx.x*blockDim.x + threadIdx.x;
    if (idx >= PROWS*DIM) return;
    int f   = idx % DIM;
    int row = idx / DIM;
    int b = row / NPATCH, n = row % NPATCH;
    int ph = n / 14, pw = n % 14;
    int c = f / 256, r = f % 256;
    int p = r / 16,  q = r % 16;
    oh[idx] = __float2half_rn(x[(((LL)b*3 + c)*224 + ph*16 + p)*224 + pw*16 + q]);
}

__global__ void assemble_k(const float* __restrict__ patch, const float* __restrict__ cls,
                           const float* __restrict__ pos, float* __restrict__ h) {
    int idx = blockIdx.x*blockDim.x + threadIdx.x;
    if (idx >= ROWS*DIM) return;
    int d = idx % DIM;
    int row = idx / DIM;
    int b = row / SEQ, s = row % SEQ;
    float v = (s == 0) ? cls[d] : patch[((LL)b*NPATCH + (s-1))*DIM + d];
    h[idx] = v + pos[s*DIM + d];
}

template<bool AFF>
__global__ void ln_half_k(const float* __restrict__ in, const float* __restrict__ g,
                          const float* __restrict__ b, fp16* __restrict__ oh) {
    int row = blockIdx.x;
    const float* xr = in + (LL)row*DIM;
    int t = threadIdx.x;
    float v0 = xr[t], v1 = xr[t+256], v2 = xr[t+512];
    __shared__ float rs[256], rss[256];
    rs[t]  = v0 + v1 + v2;
    rss[t] = v0*v0 + v1*v1 + v2*v2;
    __syncthreads();
    for (int off = 128; off > 0; off >>= 1) {
        if (t < off) { rs[t] += rs[t+off]; rss[t] += rss[t+off]; }
        __syncthreads();
    }
    float mu   = rs[0]  * (1.f/768.f);
    float rstd = rsqrtf(rss[0]*(1.f/768.f) - mu*mu + 1e-5f);
    float y[3] = { (v0-mu)*rstd, (v1-mu)*rstd, (v2-mu)*rstd };
    #pragma unroll
    for (int i = 0; i < 3; i++) {
        int d = t + i*256;
        float yy = y[i];
        if (AFF) yy = yy*g[d] + b[d];
        oh[(LL)row*DIM + d] = __float2half_rn(yy);
    }
}

// single-pass smem softmax over QUERY axis; grid (NBH, 2) x 256, 128 cols/block
// value-identical to the 3-pass global version (same op order per column)
#define SMX_SMEM (SEQ*128*4)   /* 100864 */
__global__ void softmax_smem_k(const float* __restrict__ S, fp16* __restrict__ Ph) {
    extern __shared__ float sm[];
    LL base = (LL)blockIdx.x * (SEQ*SEQP);
    int k0 = blockIdx.y * 128;
    int tid = threadIdx.x;

    for (int i = tid; i < SEQ*128; i += 256) {
        int q = i >> 7, k = i & 127;
        float v = (k0 + k < SEQ) ? S[base + (LL)q*SEQP + k0 + k] : 0.f;
        sm[q*128 + k] = v;
    }
    __syncthreads();

    if (tid < 128) {
        int k = k0 + tid;
        if (k < SEQ) {
            float mx = -1e30f;
            for (int q = 0; q < SEQ; q++) mx = fmaxf(mx, sm[q*128 + tid]);
            float sum = 0.f;
            for (int q = 0; q < SEQ; q++) sum += expf(sm[q*128 + tid] - mx);
            float inv = 1.f / sum;
            for (int q = 0; q < SEQ; q++) {
                float p = expf(sm[q*128 + tid] - mx) * inv;
                Ph[base + (LL)q*SEQP + k] = __float2half_rn(p);
            }
        } else {
            for (int q = 0; q < SEQ; q++)
                Ph[base + (LL)q*SEQP + k] = __float2half_rn(0.f);
        }
    }
}

__global__ void final_head_k(const float* __restrict__ h, const float* __restrict__ g,
                             const float* __restrict__ b, const float* __restrict__ Wc,
                             const float* __restrict__ bc, float* __restrict__ out) {
    int bi = blockIdx.x;
    const float* xr = h + (LL)bi*SEQ*DIM;
    int t = threadIdx.x;
    float v0 = xr[t], v1 = xr[t+256], v2 = xr[t+512];
    __shared__ float rs[256], rss[256];
    rs[t]  = v0 + v1 + v2;
    rss[t] = v0*v0 + v1*v1 + v2*v2;
    __syncthreads();
    for (int off = 128; off > 0; off >>= 1) {
        if (t < off) { rs[t] += rs[t+off]; rss[t] += rss[t+off]; }
        __syncthreads();
    }
    float mu   = rs[0]  * (1.f/768.f);
    float rstd = rsqrtf(rss[0]*(1.f/768.f) - mu*mu + 1e-5f);
    __shared__ float pa[NC][256];
    float a[NC] = {0.f, 0.f, 0.f, 0.f};
    float vv[3] = {v0, v1, v2};
    #pragma unroll
    for (int i = 0; i < 3; i++) {
        int d = t + i*256;
        float y = (vv[i]-mu)*rstd*g[d] + b[d];
        #pragma unroll
        for (int c = 0; c < NC; c++) a[c] = fmaf(y, Wc[d*NC + c], a[c]);
    }
    #pragma unroll
    for (int c = 0; c < NC; c++) pa[c][t] = a[c];
    __syncthreads();
    for (int off = 128; off > 0; off >>= 1) {
        if (t < off) {
            #pragma unroll
            for (int c = 0; c < NC; c++) pa[c][t] += pa[c][t+off];
        }
        __syncthreads();
    }
    if (t < NC) out[bi*NC + t] = pa[t][0] + bc[t];
}

// ---------------- orchestration ----------------
extern "C" void kernel_launch(void* const* d_in, const int* in_sizes, int n_in,
                              void* d_out, int out_size)
{
    const float* x      = (const float*)d_in[0];
    const float* Wpatch = (const float*)d_in[1];
    const float* bpatch = (const float*)d_in[2];
    const float* cls    = (const float*)d_in[3];
    const float* pos    = (const float*)d_in[4];
    const float* ln1g   = (const float*)d_in[5];
    const float* ln1b   = (const float*)d_in[6];
    const float* Wq     = (const float*)d_in[7];
    const float* bq     = (const float*)d_in[8];
    const float* Wk     = (const float*)d_in[9];
    const float* bk     = (const float*)d_in[10];
    const float* Wv     = (const float*)d_in[11];
    const float* bv     = (const float*)d_in[12];
    const float* Wo     = (const float*)d_in[13];
    const float* bo     = (const float*)d_in[14];
    const float* ln2g   = (const float*)d_in[15];
    const float* ln2b   = (const float*)d_in[16];
    const float* W1     = (const float*)d_in[17];
    const float* b1m    = (const float*)d_in[18];
    const float* W2     = (const float*)d_in[19];
    const float* b2m    = (const float*)d_in[20];
    const float* lnfg   = (const float*)d_in[21];
    const float* lnfb   = (const float*)d_in[22];
    const float* Wc     = (const float*)d_in[23];
    const float* bc     = (const float*)d_in[24];
    float* out = (float*)d_out;

    float *PO, *H, *BfL, *Part, *S;
    fp16 *Xn, *Xp, *QKV, *Cat, *Hid, *Ph, *WqkvL, *WoL, *W1L, *W2L, *Wp;
    { void* p;
      cudaGetSymbolAddress(&p, g_PO);    PO    = (float*)p;
      cudaGetSymbolAddress(&p, g_H);     H     = (float*)p;
      cudaGetSymbolAddress(&p, g_BfL);   BfL   = (float*)p;
      cudaGetSymbolAddress(&p, g_Part);  Part  = (float*)p;
      cudaGetSymbolAddress(&p, g_S);     S     = (float*)p;
      cudaGetSymbolAddress(&p, g_Xn);    Xn    = (fp16*)p;
      cudaGetSymbolAddress(&p, g_Xp);    Xp    = (fp16*)p;
      cudaGetSymbolAddress(&p, g_QKV);   QKV   = (fp16*)p;
      cudaGetSymbolAddress(&p, g_Cat);   Cat   = (fp16*)p;
      cudaGetSymbolAddress(&p, g_Hid);   Hid   = (fp16*)p;
      cudaGetSymbolAddress(&p, g_Ph);    Ph    = (fp16*)p;
      cudaGetSymbolAddress(&p, g_WqkvL); WqkvL = (fp16*)p;
      cudaGetSymbolAddress(&p, g_WoL);   WoL   = (fp16*)p;
      cudaGetSymbolAddress(&p, g_W1L);   W1L   = (fp16*)p;
      cudaGetSymbolAddress(&p, g_W2L);   W2L   = (fp16*)p;
      cudaGetSymbolAddress(&p, g_Wp);    Wp    = (fp16*)p;
    }

    static cudaStream_t sW = nullptr;
    static cudaEvent_t evFork, evPatch, evL[NLAYER];
    static int init_done = 0;
    if (!init_done) {
        cudaStreamCreateWithFlags(&sW, cudaStreamNonBlocking);
        cudaEventCreateWithFlags(&evFork,  cudaEventDisableTiming);
        cudaEventCreateWithFlags(&evPatch, cudaEventDisableTiming);
        for (int l = 0; l < NLAYER; l++)
            cudaEventCreateWithFlags(&evL[l], cudaEventDisableTiming);
        cudaFuncSetAttribute(mm1<EPI_BIAS|EPI_SPLITH>,          cudaFuncAttributeMaxDynamicSharedMemorySize, MM_SMEM);
        cudaFuncSetAttribute(mm1<EPI_BIAS|EPI_GELU|EPI_SPLITH>, cudaFuncAttributeMaxDynamicSharedMemorySize, MM_SMEM);
        cudaFuncSetAttribute(mms<EPI_BIAS, false>,              cudaFuncAttributeMaxDynamicSharedMemorySize, MS_SMEM);
        cudaFuncSetAttribute(mms<0, false>,                     cudaFuncAttributeMaxDynamicSharedMemorySize, MS_SMEM);
        cudaFuncSetAttribute(mms<EPI_SPLITH, true>,             cudaFuncAttributeMaxDynamicSharedMemorySize, MS_SMEM);
        cudaFuncSetAttribute(mms<EPI_BIAS|EPI_RES, false>,      cudaFuncAttributeMaxDynamicSharedMemorySize, MS_SMEM);
        cudaFuncSetAttribute(softmax_smem_k,                    cudaFuncAttributeMaxDynamicSharedMemorySize, SMX_SMEM);
        init_done = 1;
    }

    const float inv_scale = 1.0f / sqrtf(768.0f);

    // ================= fork weight-prep stream =================
    cudaEventRecord(evFork, 0);
    cudaStreamWaitEvent(sW, evFork, 0);

    conv_k<<<((DIM*DIM/4) + 255)/256, 256, 0, sW>>>((const float4*)Wpatch, Wp, DIM*DIM/4);
    cudaEventRecord(evPatch, sW);

    for (int l = 0; l < NLAYER; l++) {
        const float* Wq_l = Wq + (LL)l*NH*DIM*DIM;
        const float* Wk_l = Wk + (LL)l*NH*DIM*DIM;
        const float* Wv_l = Wv + (LL)l*NH*DIM*DIM;
        fold_qkv_w<<<dim3(DIM/32, DIM/32, 3*NH), dim3(32,8), 0, sW>>>(
            Wq_l, Wk_l, Wv_l, ln1g + (LL)l*NH*DIM, ln1b + (LL)l*NH*DIM,
            WqkvL + (LL)l*3*HDK*DIM, Part);
        reduce_bf<<<HDK3/256, 256, 0, sW>>>(
            Part, bq + (LL)l*NH*DIM, bk + (LL)l*NH*DIM, bv + (LL)l*NH*DIM,
            BfL + (LL)l*HDK3);
        tconv_k<<<dim3(HDK/32, DIM/32), dim3(32,8), 0, sW>>>(
            Wo + (LL)l*HDK*DIM, WoL + (LL)l*HDK*DIM, HDK, DIM);
        tconv_k<<<dim3(DIM/32, MLP/32), dim3(32,8), 0, sW>>>(
            W1 + (LL)l*DIM*MLP, W1L + (LL)l*DIM*MLP, DIM, MLP);
        tconv_k<<<dim3(MLP/32, DIM/32), dim3(32,8), 0, sW>>>(
            W2 + (LL)l*MLP*DIM, W2L + (LL)l*MLP*DIM, MLP, DIM);
        cudaEventRecord(evL[l], sW);
    }

    // ================= main stream =================
    im2col_half<<<(PROWS*DIM + 255)/256, 256>>>(x, Xp);
    cudaStreamWaitEvent(0, evPatch, 0);
    mms<EPI_BIAS, false><<<dim3(6, 49, 1), 256, MS_SMEM>>>(
        Xp, Wp, PO, nullptr, bpatch, nullptr,
        PROWS, DIM, DIM, DIM, DIM, DIM, DIM,
        1, 0, 0, 0, 0, 0, 0, 1.f);
    assemble_k<<<(ROWS*DIM + 255)/256, 256>>>(PO, cls, pos, H);

    for (int l = 0; l < NLAYER; l++) {
        const fp16* Wqkv_l = WqkvL + (LL)l*3*HDK*DIM;
        const float* Bf_l  = BfL + (LL)l*HDK3;
        const fp16* Wo_l   = WoL + (LL)l*HDK*DIM;
        const fp16* W1_l   = W1L + (LL)l*DIM*MLP;
        const fp16* W2_l   = W2L + (LL)l*MLP*DIM;
        const float* bo_l  = bo  + (LL)l*DIM;
        const float* g2_l  = ln2g + (LL)l*DIM;
        const float* b2_l  = ln2b + (LL)l*DIM;
        const float* b1_l  = b1m + (LL)l*MLP;
        const float* bb2_l = b2m + (LL)l*DIM;

        ln_half_k<false><<<ROWS, 256>>>(H, nullptr, nullptr, Xn);

        cudaStreamWaitEvent(0, evL[l], 0);

        mm1<EPI_BIAS|EPI_SPLITH><<<dim3(HDK3/256, 25, 1), 512, MM_SMEM>>>(
            Xn, Wqkv_l, nullptr, QKV, Bf_l, nullptr,
            ROWS, HDK3, HDK3, DIM, DIM, DIM, HDK3, 1.f);

        // scores = Q·K^T / sqrt(768)
        mms<0, false><<<dim3(2, 4, NBH), 256, MS_SMEM>>>(
            QKV, QKV + HDK, S, nullptr, nullptr, nullptr,
            SEQ, SEQ, SEQ, DIM,
            HDK3, HDK3, SEQP,
            NH, (LL)SEQ*HDK3, (LL)DIM, (LL)SEQ*HDK3, (LL)DIM,
            (LL)NH*SEQ*SEQP, (LL)SEQ*SEQP, inv_scale);

        softmax_smem_k<<<dim3(NBH, 2), 256, SMX_SMEM>>>(S, Ph);

        // av = P·V (trans-B) -> cat layout
        mms<EPI_SPLITH, true><<<dim3(6, 4, NBH), 256, MS_SMEM>>>(
            Ph, QKV + 2*HDK, nullptr, Cat, nullptr, nullptr,
            SEQ, DIM, SEQ, SEQP,
            SEQP, HDK3, HDK,
            NH, (LL)NH*SEQ*SEQP, (LL)SEQ*SEQP, (LL)SEQ*HDK3, (LL)DIM,
            (LL)SEQ*HDK, (LL)DIM, 1.f);

        // out proj + bias + residual -> H
        mms<EPI_BIAS|EPI_RES, false><<<dim3(6, 50, 1), 256, MS_SMEM>>>(
            Cat, Wo_l, H, nullptr, bo_l, H,
            ROWS, DIM, DIM, HDK, HDK, HDK, DIM,
            1, 0, 0, 0, 0, 0, 0, 1.f);

        // MLP
        ln_half_k<true><<<ROWS, 256>>>(H, g2_l, b2_l, Xn);
        mm1<EPI_BIAS|EPI_GELU|EPI_SPLITH><<<dim3(MLP/256, 25, 1), 512, MM_SMEM>>>(
            Xn, W1_l, nullptr, Hid, b1_l, nullptr,
            ROWS, MLP, MLP, DIM, DIM, DIM, MLP, 1.f);

        mms<EPI_BIAS|EPI_RES, false><<<dim3(6, 50, 1), 256, MS_SMEM>>>(
            Hid, W2_l, H, nullptr, bb2_l, H,
            ROWS, DIM, DIM, MLP, MLP, MLP, DIM,
            1, 0, 0, 0, 0, 0, 0, 1.f);
    }

    // ---- final LN on CLS + classifier ----
    final_head_k<<<BATCH, 256>>>(H, lnfg, lnfb, Wc, bc, out);
}

// round 17
// speedup vs baseline: 1.0157x; 1.0157x over previous
#include <cuda_runtime.h>
#include <cuda_fp16.h>
#include <math.h>
#include <stdint.h>

typedef long long LL;
typedef __half fp16;

#define BATCH   16
#define SEQ     197
#define SEQP    256
#define NPATCH  196
#define DIM     768
#define NH      12
#define HDK     9216
#define HDK3    27648
#define MLP     3072
#define ROWS    (BATCH*SEQ)     /* 3152 */
#define PROWS   (BATCH*NPATCH)  /* 3136 */
#define NLAYER  4
#define NC      4
#define NBH     (BATCH*NH)      /* 192 */

// ---------------- scratch (device globals) ----------------
__device__ float g_PO [PROWS*DIM];
__device__ float g_H  [ROWS*DIM];
__device__ float g_BfL[(LL)NLAYER*HDK3];
__device__ float g_Part[(LL)24*HDK3];
__device__ float g_S  [(LL)NBH*SEQ*SEQP];

__device__ fp16 g_Xn  [ROWS*DIM];
__device__ fp16 g_Xp  [PROWS*DIM];
__device__ fp16 g_QKV [(LL)ROWS*HDK3];
__device__ fp16 g_Cat [(LL)ROWS*HDK];
__device__ fp16 g_Hid [(LL)ROWS*MLP];
__device__ fp16 g_Ph  [(LL)NBH*SEQ*SEQP];
__device__ fp16 g_WqkvL[(LL)NLAYER*3*HDK*DIM];
__device__ fp16 g_WoL [(LL)NLAYER*HDK*DIM];
__device__ fp16 g_W1L [(LL)NLAYER*DIM*MLP];
__device__ fp16 g_W2L [(LL)NLAYER*MLP*DIM];
__device__ fp16 g_Wp  [DIM*DIM];

// ---------------- helpers ----------------
__device__ __forceinline__ uint32_t smem_u32(const void* p) {
    uint32_t a;
    asm("{ .reg .u64 t; cvta.to.shared.u64 t, %1; cvt.u32.u64 %0, t; }" : "=r"(a) : "l"(p));
    return a;
}
__device__ __forceinline__ uint32_t swz(uint32_t off) { return off ^ ((off >> 3) & 0x70); }

__device__ __forceinline__ void cp16z(uint32_t dst, const void* src, uint32_t sz) {
    asm volatile("cp.async.cg.shared.global [%0], [%1], 16, %2;\n"
                 :: "r"(dst), "l"(src), "r"(sz) : "memory");
}
__device__ __forceinline__ void cp_commit() {
    asm volatile("cp.async.commit_group;\n" ::: "memory");
}
__device__ __forceinline__ void ldsm4(uint32_t* r, uint32_t addr) {
    asm volatile("ldmatrix.sync.aligned.m8n8.x4.shared.b16 {%0,%1,%2,%3}, [%4];\n"
                 : "=r"(r[0]), "=r"(r[1]), "=r"(r[2]), "=r"(r[3]) : "r"(addr));
}
__device__ __forceinline__ void ldsm4t(uint32_t* r, uint32_t addr) {
    asm volatile("ldmatrix.sync.aligned.m8n8.x4.trans.shared.b16 {%0,%1,%2,%3}, [%4];\n"
                 : "=r"(r[0]), "=r"(r[1]), "=r"(r[2]), "=r"(r[3]) : "r"(addr));
}
__device__ __forceinline__ void mma16816(float* c, const uint32_t* a, const uint32_t* b) {
    asm volatile(
        "mma.sync.aligned.m16n8k16.row.col.f32.f16.f16.f32 "
        "{%0,%1,%2,%3}, {%4,%5,%6,%7}, {%8,%9}, {%0,%1,%2,%3};\n"
        : "+f"(c[0]), "+f"(c[1]), "+f"(c[2]), "+f"(c[3])
        : "r"(a[0]), "r"(a[1]), "r"(a[2]), "r"(a[3]), "r"(b[0]), "r"(b[1]));
}

#define EPI_BIAS   1
#define EPI_RES    2
#define EPI_GELU   4
#define EPI_SPLITH 16

// ================= mm1: 512 thr, BM=128 x BN=256, 4-stage ===================
#define MM_SMEM 196608

__device__ __forceinline__ void load_tile1(uint32_t stg,
    const fp16* __restrict__ A, const fp16* __restrict__ B,
    int bm, int bn, int M, int Brows, int lda, int ldb, int k0, int tid)
{
    constexpr uint32_t SB = 16384;
    #pragma unroll
    for (int it = 0; it < 2; it++) {
        int i = tid + it*512;
        int row = i >> 3, j = i & 7;
        int gm = bm + row;
        uint32_t sz = (gm < M) ? 16u : 0u;
        int gmc = (gm < M) ? gm : 0;
        const char* p = (const char*)(A + (LL)gmc*lda + k0) + j*16;
        cp16z(stg + swz((uint32_t)row*128u + (uint32_t)j*16u), p, sz);
    }
    #pragma unroll
    for (int it = 0; it < 4; it++) {
        int i = tid + it*512;
        int row = i >> 3, j = i & 7;
        int gn = bn + row;
        uint32_t sz = (gn < Brows) ? 16u : 0u;
        int gnc = (gn < Brows) ? gn : 0;
        const char* p = (const char*)(B + (LL)gnc*ldb + k0) + j*16;
        cp16z(stg + SB + swz((uint32_t)row*128u + (uint32_t)j*16u), p, sz);
    }
}

template<int EPI>
__global__ void __launch_bounds__(512, 1)
mm1(const fp16* __restrict__ A, const fp16* __restrict__ B,
    float* __restrict__ C, fp16* __restrict__ Ch,
    const float* __restrict__ bias, const float* __restrict__ res,
    int M, int N, int Brows, int K, int lda, int ldb, int ldc, float alpha)
{
    constexpr uint32_t SB = 16384;
    constexpr int STG = 49152, NSTG = 4;

    extern __shared__ char smem[];
    uint32_t sb = smem_u32(smem);
    const int tid  = threadIdx.x;
    const int wid  = tid >> 5;
    const int lane = tid & 31;
    const int bm = blockIdx.y * 128;
    const int bn = blockIdx.x * 256;

    const int m_warp = (wid & 3) * 32;
    const int n_warp = (wid >> 2) * 64;

    float acc[2][8][4];
    #pragma unroll
    for (int mt = 0; mt < 2; mt++)
        #pragma unroll
        for (int nt = 0; nt < 8; nt++)
            #pragma unroll
            for (int e = 0; e < 4; e++) acc[mt][nt][e] = 0.f;

    const int NCH = K >> 6;

    #pragma unroll
    for (int s = 0; s < NSTG-1; s++) {
        if (s < NCH)
            load_tile1(sb + s*STG, A, B, bm, bn, M, Brows, lda, ldb, s*64, tid);
        cp_commit();
    }

    const int lar = lane & 15;
    const int lac = (lane >> 4) * 16;
    const int lbr = ((lane & 16) >> 1) + (lane & 7);
    const int lbc = ((lane >> 3) & 1) * 16;

    for (int c = 0; c < NCH; c++) {
        if (c + NSTG-1 < NCH)
            load_tile1(sb + ((c + NSTG-1) % NSTG)*STG,
                       A, B, bm, bn, M, Brows, lda, ldb, (c + NSTG-1)*64, tid);
        cp_commit();
        asm volatile("cp.async.wait_group %0;\n" :: "n"(NSTG-1) : "memory");
        __syncthreads();

        uint32_t stg = sb + (c % NSTG)*STG;
        #pragma unroll
        for (int ks = 0; ks < 4; ks++) {
            uint32_t a[2][4];
            #pragma unroll
            for (int mt = 0; mt < 2; mt++) {
                uint32_t off = swz((uint32_t)(m_warp + mt*16 + lar)*128u + ks*32 + lac);
                ldsm4(a[mt], stg + off);
            }
            #pragma unroll
            for (int p = 0; p < 4; p++) {
                uint32_t rb[4];
                uint32_t off = swz((uint32_t)(n_warp + p*16 + lbr)*128u + ks*32 + lbc);
                ldsm4(rb, stg + SB + off);
                #pragma unroll
                for (int mt = 0; mt < 2; mt++) {
                    mma16816(acc[mt][2*p],   a[mt], rb);
                    mma16816(acc[mt][2*p+1], a[mt], rb+2);
                }
            }
        }
        __syncthreads();
    }

    #pragma unroll
    for (int mt = 0; mt < 2; mt++) {
        #pragma unroll
        for (int half = 0; half < 2; half++) {
            int m = bm + m_warp + mt*16 + (lane >> 2) + half*8;
            if (m >= M) continue;
            #pragma unroll
            for (int nt = 0; nt < 8; nt++) {
                int n = bn + n_warp + nt*8 + (lane & 3)*2;
                if (n >= N) continue;
                float v0 = acc[mt][nt][half*2 + 0] * alpha;
                float v1 = acc[mt][nt][half*2 + 1] * alpha;
                if (EPI & EPI_BIAS) { v0 += __ldg(&bias[n]); v1 += __ldg(&bias[n+1]); }
                if (EPI & EPI_RES) {
                    const float2 rv = *(const float2*)(res + (LL)m*ldc + n);
                    v0 += rv.x; v1 += rv.y;
                }
                if (EPI & EPI_GELU) {
                    v0 = 0.5f*v0*(1.f + erff(v0*0.70710678118654752440f));
                    v1 = 0.5f*v1*(1.f + erff(v1*0.70710678118654752440f));
                }
                if (EPI & EPI_SPLITH) {
                    __half2 ph; ph.x = __float2half_rn(v0); ph.y = __float2half_rn(v1);
                    *(__half2*)(Ch + (LL)m*ldc + n) = ph;
                } else {
                    *(float2*)(C + (LL)m*ldc + n) = make_float2(v0, v1);
                }
            }
        }
    }
}

// ================= mms: 256 thr, BM=64 x BN=128, 3-stage, 3 CTA/SM ==========
#define MS_SMEM 73728

template<bool BT>
__device__ __forceinline__ void load_tile_s(uint32_t stg,
    const fp16* __restrict__ A, const fp16* __restrict__ B,
    int bm, int bn, int M, int Brows, int lda, int ldb, int k0, int tid)
{
    constexpr uint32_t SB = 8192;
    #pragma unroll
    for (int it = 0; it < 2; it++) {
        int i = tid + it*256;
        int row = i >> 3, j = i & 7;
        int gm = bm + row;
        uint32_t sz = (gm < M) ? 16u : 0u;
        int gmc = (gm < M) ? gm : 0;
        const char* p = (const char*)(A + (LL)gmc*lda + k0) + j*16;
        cp16z(stg + swz((uint32_t)row*128u + (uint32_t)j*16u), p, sz);
    }
    if (!BT) {
        #pragma unroll
        for (int it = 0; it < 4; it++) {
            int i = tid + it*256;
            int row = i >> 3, j = i & 7;
            int gn = bn + row;
            uint32_t sz = (gn < Brows) ? 16u : 0u;
            int gnc = (gn < Brows) ? gn : 0;
            const char* p = (const char*)(B + (LL)gnc*ldb + k0) + j*16;
            cp16z(stg + SB + swz((uint32_t)row*128u + (uint32_t)j*16u), p, sz);
        }
    } else {
        #pragma unroll
        for (int it = 0; it < 4; it++) {
            int i = tid + it*256;
            int row = i >> 4, j = i & 15;
            int gk = k0 + row;
            uint32_t sz = (gk < Brows) ? 16u : 0u;
            int gkc = (gk < Brows) ? gk : 0;
            const char* p = (const char*)(B + (LL)gkc*ldb + bn) + j*16;
            uint32_t so = (uint32_t)row*256u + (((uint32_t)j*16u) ^ (((uint32_t)row & 7u) << 4));
            cp16z(stg + SB + so, p, sz);
        }
    }
}

template<int EPI, bool BT>
__global__ void __launch_bounds__(256, 3)
mms(const fp16* __restrict__ A, const fp16* __restrict__ B,
    float* __restrict__ C, fp16* __restrict__ Ch,
    const float* __restrict__ bias, const float* __restrict__ res,
    int M, int N, int Brows, int K, int lda, int ldb, int ldc,
    int zdiv, LL sA0, LL sA1, LL sB0, LL sB1, LL sC0, LL sC1,
    float alpha)
{
    constexpr uint32_t SB = 8192;
    constexpr int STG = 24576, NSTG = 3;

    extern __shared__ char smem[];
    uint32_t sb = smem_u32(smem);
    const int tid  = threadIdx.x;
    const int wid  = tid >> 5;
    const int lane = tid & 31;
    const int bm = blockIdx.y * 64;
    const int bn = blockIdx.x * 128;
    const int zo = blockIdx.z / zdiv, zi = blockIdx.z - zo*zdiv;
    A += zo*sA0 + zi*sA1;
    B += zo*sB0 + zi*sB1;
    const LL cbase = zo*sC0 + zi*sC1;

    const int m_warp = (wid & 1) * 32;
    const int n_warp = (wid >> 1) * 32;

    float acc[2][4][4];
    #pragma unroll
    for (int mt = 0; mt < 2; mt++)
        #pragma unroll
        for (int nt = 0; nt < 4; nt++)
            #pragma unroll
            for (int e = 0; e < 4; e++) acc[mt][nt][e] = 0.f;

    const int NCH = K >> 6;

    #pragma unroll
    for (int s = 0; s < NSTG-1; s++) {
        if (s < NCH)
            load_tile_s<BT>(sb + s*STG, A, B, bm, bn, M, Brows, lda, ldb, s*64, tid);
        cp_commit();
    }

    const int lar = lane & 15;
    const int lac = (lane >> 4) * 16;
    const int lbr = ((lane & 16) >> 1) + (lane & 7);
    const int lbc = ((lane >> 3) & 1) * 16;

    for (int c = 0; c < NCH; c++) {
        if (c + NSTG-1 < NCH)
            load_tile_s<BT>(sb + ((c + NSTG-1) % NSTG)*STG,
                            A, B, bm, bn, M, Brows, lda, ldb, (c + NSTG-1)*64, tid);
        cp_commit();
        asm volatile("cp.async.wait_group %0;\n" :: "n"(NSTG-1) : "memory");
        __syncthreads();

        uint32_t stg = sb + (c % NSTG)*STG;
        #pragma unroll
        for (int ks = 0; ks < 4; ks++) {
            uint32_t a[2][4];
            #pragma unroll
            for (int mt = 0; mt < 2; mt++) {
                uint32_t off = swz((uint32_t)(m_warp + mt*16 + lar)*128u + ks*32 + lac);
                ldsm4(a[mt], stg + off);
            }
            #pragma unroll
            for (int p = 0; p < 2; p++) {
                uint32_t rb[4];
                if (!BT) {
                    uint32_t off = swz((uint32_t)(n_warp + p*16 + lbr)*128u + ks*32 + lbc);
                    ldsm4(rb, stg + SB + off);
                } else {
                    uint32_t row = (uint32_t)(ks*16 + (lane & 15));
                    uint32_t nb  = (uint32_t)((n_warp + p*16)*2) + (((uint32_t)lane >> 4) << 4);
                    uint32_t off = row*256u + (nb ^ ((row & 7u) << 4));
                    ldsm4t(rb, stg + SB + off);
                }
                #pragma unroll
                for (int mt = 0; mt < 2; mt++) {
                    mma16816(acc[mt][2*p],   a[mt], rb);
                    mma16816(acc[mt][2*p+1], a[mt], rb+2);
                }
            }
        }
        __syncthreads();
    }

    #pragma unroll
    for (int mt = 0; mt < 2; mt++) {
        #pragma unroll
        for (int half = 0; half < 2; half++) {
            int m = bm + m_warp + mt*16 + (lane >> 2) + half*8;
            if (m >= M) continue;
            #pragma unroll
            for (int nt = 0; nt < 4; nt++) {
                int n = bn + n_warp + nt*8 + (lane & 3)*2;
                if (n >= N) continue;
                float v0 = acc[mt][nt][half*2 + 0] * alpha;
                float v1 = acc[mt][nt][half*2 + 1] * alpha;
                if (EPI & EPI_BIAS) { v0 += __ldg(&bias[n]); v1 += __ldg(&bias[n+1]); }
                if (EPI & EPI_RES) {
                    const float2 rv = *(const float2*)(res + (LL)m*ldc + n);
                    v0 += rv.x; v1 += rv.y;
                }
                if (EPI & EPI_GELU) {
                    v0 = 0.5f*v0*(1.f + erff(v0*0.70710678118654752440f));
                    v1 = 0.5f*v1*(1.f + erff(v1*0.70710678118654752440f));
                }
                if (EPI & EPI_SPLITH) {
                    __half2 ph; ph.x = __float2half_rn(v0); ph.y = __float2half_rn(v1);
                    *(__half2*)(Ch + cbase + (LL)m*ldc + n) = ph;
                } else {
                    *(float2*)(C + cbase + (LL)m*ldc + n) = make_float2(v0, v1);
                }
            }
        }
    }
}

// ---------------- conversion / small kernels ----------------
__global__ void conv_k(const float4* __restrict__ in, fp16* __restrict__ out, int n4) {
    int i = blockIdx.x*blockDim.x + threadIdx.x;
    if (i >= n4) return;
    float4 v = in[i];
    __half2 a, b;
    a.x = __float2half_rn(v.x); a.y = __float2half_rn(v.y);
    b.x = __float2half_rn(v.z); b.y = __float2half_rn(v.w);
    *(__half2*)(out + i*4)     = a;
    *(__half2*)(out + i*4 + 2) = b;
}

__global__ void fold_qkv_w(const float* __restrict__ Wq, const float* __restrict__ Wk,
                           const float* __restrict__ Wv, const float* __restrict__ g,
                           const float* __restrict__ b1,
                           fp16* __restrict__ out, float* __restrict__ part) {
    __shared__ float t[32][33];
    __shared__ float red[8][32];
    int z = blockIdx.z;
    int m = z / NH, h = z % NH;
    const float* W = ((m == 0) ? Wq : (m == 1) ? Wk : Wv) + (LL)h*DIM*DIM;
    int d0 = blockIdx.y*32, k0 = blockIdx.x*32;
    const float* b1h = b1 + (LL)h*DIM;
    float pb = 0.f;
    for (int i = threadIdx.y; i < 32; i += 8) {
        float w = W[(LL)(d0+i)*DIM + k0 + threadIdx.x];
        t[i][threadIdx.x] = w * g[h*DIM + d0 + i];
        pb = fmaf(b1h[d0 + i], w, pb);
    }
    red[threadIdx.y][threadIdx.x] = pb;
    __syncthreads();
    for (int i = threadIdx.y; i < 32; i += 8)
        out[(LL)(m*HDK + h*DIM + k0 + i)*DIM + d0 + threadIdx.x] = __float2half_rn(t[threadIdx.x][i]);
    if (threadIdx.y == 0) {
        float s = red[0][threadIdx.x];
        #pragma unroll
        for (int j = 1; j < 8; j++) s += red[j][threadIdx.x];
        part[(LL)blockIdx.y*HDK3 + m*HDK + h*DIM + k0 + threadIdx.x] = s;
    }
}

__global__ void reduce_bf(const float* __restrict__ part,
                          const float* __restrict__ bq, const float* __restrict__ bk,
                          const float* __restrict__ bv, float* __restrict__ Bf) {
    int n = blockIdx.x*256 + threadIdx.x;
    if (n >= HDK3) return;
    int m = n / HDK, r = n - m*HDK;
    float s = ((m == 0) ? bq : (m == 1) ? bk : bv)[r];
    #pragma unroll 8
    for (int j = 0; j < 24; j++) s += part[(LL)j*HDK3 + n];
    Bf[n] = s;
}

__global__ void tconv_k(const float* __restrict__ W, fp16* __restrict__ out, int K, int N) {
    __shared__ float t[32][33];
    int k0 = blockIdx.x*32, n0 = blockIdx.y*32;
    for (int i = threadIdx.y; i < 32; i += 8)
        t[i][threadIdx.x] = W[(LL)(k0+i)*N + n0 + threadIdx.x];
    __syncthreads();
    for (int i = threadIdx.y; i < 32; i += 8)
        out[(LL)(n0+i)*K + k0 + threadIdx.x] = __float2half_rn(t[threadIdx.x][i]);
}

__global__ void im2col_half(const float* __restrict__ x, fp16* __restrict__ oh) {
    int idx = blockIdx.x*blockDim.x + threadIdx.x;
    if (idx >= PROWS*DIM) return;
    int f   = idx % DIM;
    int row = idx / DIM;
    int b = row / NPATCH, n = row % NPATCH;
    int ph = n / 14, pw = n % 14;
    int c = f / 256, r = f % 256;
    int p = r / 16,  q = r % 16;
    oh[idx] = __float2half_rn(x[(((LL)b*3 + c)*224 + ph*16 + p)*224 + pw*16 + q]);
}

__global__ void assemble_k(const float* __restrict__ patch, const float* __restrict__ cls,
                           const float* __restrict__ pos, float* __restrict__ h) {
    int idx = blockIdx.x*blockDim.x + threadIdx.x;
    if (idx >= ROWS*DIM) return;
    int d = idx % DIM;
    int row = idx / DIM;
    int b = row / SEQ, s = row % SEQ;
    float v = (s == 0) ? cls[d] : patch[((LL)b*NPATCH + (s-1))*DIM + d];
    h[idx] = v + pos[s*DIM + d];
}

template<bool AFF>
__global__ void ln_half_k(const float* __restrict__ in, const float* __restrict__ g,
                          const float* __restrict__ b, fp16* __restrict__ oh) {
    int row = blockIdx.x;
    const float* xr = in + (LL)row*DIM;
    int t = threadIdx.x;
    float v0 = xr[t], v1 = xr[t+256], v2 = xr[t+512];
    __shared__ float rs[256], rss[256];
    rs[t]  = v0 + v1 + v2;
    rss[t] = v0*v0 + v1*v1 + v2*v2;
    __syncthreads();
    for (int off = 128; off > 0; off >>= 1) {
        if (t < off) { rs[t] += rs[t+off]; rss[t] += rss[t+off]; }
        __syncthreads();
    }
    float mu   = rs[0]  * (1.f/768.f);
    float rstd = rsqrtf(rss[0]*(1.f/768.f) - mu*mu + 1e-5f);
    float y[3] = { (v0-mu)*rstd, (v1-mu)*rstd, (v2-mu)*rstd };
    #pragma unroll
    for (int i = 0; i < 3; i++) {
        int d = t + i*256;
        float yy = y[i];
        if (AFF) yy = yy*g[d] + b[d];
        oh[(LL)row*DIM + d] = __float2half_rn(yy);
    }
}

__global__ void softmax_half_k(const float* __restrict__ S, fp16* __restrict__ Ph) {
    LL base = (LL)blockIdx.x * (SEQ*SEQP);
    int k = blockIdx.y*128 + threadIdx.x;
    if (k >= SEQ) {
        for (int q = 0; q < SEQ; q++) Ph[base + (LL)q*SEQP + k] = __float2half_rn(0.f);
        return;
    }
    float mx = -1e30f;
    for (int q = 0; q < SEQ; q++) mx = fmaxf(mx, S[base + (LL)q*SEQP + k]);
    float sum = 0.f;
    for (int q = 0; q < SEQ; q++) sum += expf(S[base + (LL)q*SEQP + k] - mx);
    float inv = 1.f / sum;
    for (int q = 0; q < SEQ; q++) {
        float p = expf(S[base + (LL)q*SEQP + k] - mx) * inv;
        Ph[base + (LL)q*SEQP + k] = __float2half_rn(p);
    }
}

__global__ void final_head_k(const float* __restrict__ h, const float* __restrict__ g,
                             const float* __restrict__ b, const float* __restrict__ Wc,
                             const float* __restrict__ bc, float* __restrict__ out) {
    int bi = blockIdx.x;
    const float* xr = h + (LL)bi*SEQ*DIM;
    int t = threadIdx.x;
    float v0 = xr[t], v1 = xr[t+256], v2 = xr[t+512];
    __shared__ float rs[256], rss[256];
    rs[t]  = v0 + v1 + v2;
    rss[t] = v0*v0 + v1*v1 + v2*v2;
    __syncthreads();
    for (int off = 128; off > 0; off >>= 1) {
        if (t < off) { rs[t] += rs[t+off]; rss[t] += rss[t+off]; }
        __syncthreads();
    }
    float mu   = rs[0]  * (1.f/768.f);
    float rstd = rsqrtf(rss[0]*(1.f/768.f) - mu*mu + 1e-5f);
    __shared__ float pa[NC][256];
    float a[NC] = {0.f, 0.f, 0.f, 0.f};
    float vv[3] = {v0, v1, v2};
    #pragma unroll
    for (int i = 0; i < 3; i++) {
        int d = t + i*256;
        float y = (vv[i]-mu)*rstd*g[d] + b[d];
        #pragma unroll
        for (int c = 0; c < NC; c++) a[c] = fmaf(y, Wc[d*NC + c], a[c]);
    }
    #pragma unroll
    for (int c = 0; c < NC; c++) pa[c][t] = a[c];
    __syncthreads();
    for (int off = 128; off > 0; off >>= 1) {
        if (t < off) {
            #pragma unroll
            for (int c = 0; c < NC; c++) pa[c][t] += pa[c][t+off];
        }
        __syncthreads();
    }
    if (t < NC) out[bi*NC + t] = pa[t][0] + bc[t];
}

// ---------------- orchestration ----------------
extern "C" void kernel_launch(void* const* d_in, const int* in_sizes, int n_in,
                              void* d_out, int out_size)
{
    const float* x      = (const float*)d_in[0];
    const float* Wpatch = (const float*)d_in[1];
    const float* bpatch = (const float*)d_in[2];
    const float* cls    = (const float*)d_in[3];
    const float* pos    = (const float*)d_in[4];
    const float* ln1g   = (const float*)d_in[5];
    const float* ln1b   = (const float*)d_in[6];
    const float* Wq     = (const float*)d_in[7];
    const float* bq     = (const float*)d_in[8];
    const float* Wk     = (const float*)d_in[9];
    const float* bk     = (const float*)d_in[10];
    const float* Wv     = (const float*)d_in[11];
    const float* bv     = (const float*)d_in[12];
    const float* Wo     = (const float*)d_in[13];
    const float* bo     = (const float*)d_in[14];
    const float* ln2g   = (const float*)d_in[15];
    const float* ln2b   = (const float*)d_in[16];
    const float* W1     = (const float*)d_in[17];
    const float* b1m    = (const float*)d_in[18];
    const float* W2     = (const float*)d_in[19];
    const float* b2m    = (const float*)d_in[20];
    const float* lnfg   = (const float*)d_in[21];
    const float* lnfb   = (const float*)d_in[22];
    const float* Wc     = (const float*)d_in[23];
    const float* bc     = (const float*)d_in[24];
    float* out = (float*)d_out;

    float *PO, *H, *BfL, *Part, *S;
    fp16 *Xn, *Xp, *QKV, *Cat, *Hid, *Ph, *WqkvL, *WoL, *W1L, *W2L, *Wp;
    { void* p;
      cudaGetSymbolAddress(&p, g_PO);    PO    = (float*)p;
      cudaGetSymbolAddress(&p, g_H);     H     = (float*)p;
      cudaGetSymbolAddress(&p, g_BfL);   BfL   = (float*)p;
      cudaGetSymbolAddress(&p, g_Part);  Part  = (float*)p;
      cudaGetSymbolAddress(&p, g_S);     S     = (float*)p;
      cudaGetSymbolAddress(&p, g_Xn);    Xn    = (fp16*)p;
      cudaGetSymbolAddress(&p, g_Xp);    Xp    = (fp16*)p;
      cudaGetSymbolAddress(&p, g_QKV);   QKV   = (fp16*)p;
      cudaGetSymbolAddress(&p, g_Cat);   Cat   = (fp16*)p;
      cudaGetSymbolAddress(&p, g_Hid);   Hid   = (fp16*)p;
      cudaGetSymbolAddress(&p, g_Ph);    Ph    = (fp16*)p;
      cudaGetSymbolAddress(&p, g_WqkvL); WqkvL = (fp16*)p;
      cudaGetSymbolAddress(&p, g_WoL);   WoL   = (fp16*)p;
      cudaGetSymbolAddress(&p, g_W1L);   W1L   = (fp16*)p;
      cudaGetSymbolAddress(&p, g_W2L);   W2L   = (fp16*)p;
      cudaGetSymbolAddress(&p, g_Wp);    Wp    = (fp16*)p;
    }

    static cudaStream_t sW = nullptr;
    static cudaEvent_t evFork, evPatch, evL[NLAYER];
    static int init_done = 0;
    if (!init_done) {
        cudaStreamCreateWithFlags(&sW, cudaStreamNonBlocking);
        cudaEventCreateWithFlags(&evFork,  cudaEventDisableTiming);
        cudaEventCreateWithFlags(&evPatch, cudaEventDisableTiming);
        for (int l = 0; l < NLAYER; l++)
            cudaEventCreateWithFlags(&evL[l], cudaEventDisableTiming);
        cudaFuncSetAttribute(mm1<EPI_BIAS|EPI_SPLITH>,          cudaFuncAttributeMaxDynamicSharedMemorySize, MM_SMEM);
        cudaFuncSetAttribute(mm1<EPI_BIAS|EPI_GELU|EPI_SPLITH>, cudaFuncAttributeMaxDynamicSharedMemorySize, MM_SMEM);
        cudaFuncSetAttribute(mms<EPI_BIAS, false>,              cudaFuncAttributeMaxDynamicSharedMemorySize, MS_SMEM);
        cudaFuncSetAttribute(mms<0, false>,                     cudaFuncAttributeMaxDynamicSharedMemorySize, MS_SMEM);
        cudaFuncSetAttribute(mms<EPI_SPLITH, true>,             cudaFuncAttributeMaxDynamicSharedMemorySize, MS_SMEM);
        cudaFuncSetAttribute(mms<EPI_BIAS|EPI_RES, false>,      cudaFuncAttributeMaxDynamicSharedMemorySize, MS_SMEM);
        init_done = 1;
    }

    const float inv_scale = 1.0f / sqrtf(768.0f);

    // ================= fork weight-prep stream =================
    cudaEventRecord(evFork, 0);
    cudaStreamWaitEvent(sW, evFork, 0);

    conv_k<<<((DIM*DIM/4) + 255)/256, 256, 0, sW>>>((const float4*)Wpatch, Wp, DIM*DIM/4);
    cudaEventRecord(evPatch, sW);

    for (int l = 0; l < NLAYER; l++) {
        const float* Wq_l = Wq + (LL)l*NH*DIM*DIM;
        const float* Wk_l = Wk + (LL)l*NH*DIM*DIM;
        const float* Wv_l = Wv + (LL)l*NH*DIM*DIM;
        fold_qkv_w<<<dim3(DIM/32, DIM/32, 3*NH), dim3(32,8), 0, sW>>>(
            Wq_l, Wk_l, Wv_l, ln1g + (LL)l*NH*DIM, ln1b + (LL)l*NH*DIM,
            WqkvL + (LL)l*3*HDK*DIM, Part);
        reduce_bf<<<HDK3/256, 256, 0, sW>>>(
            Part, bq + (LL)l*NH*DIM, bk + (LL)l*NH*DIM, bv + (LL)l*NH*DIM,
            BfL + (LL)l*HDK3);
        tconv_k<<<dim3(HDK/32, DIM/32), dim3(32,8), 0, sW>>>(
            Wo + (LL)l*HDK*DIM, WoL + (LL)l*HDK*DIM, HDK, DIM);
        tconv_k<<<dim3(DIM/32, MLP/32), dim3(32,8), 0, sW>>>(
            W1 + (LL)l*DIM*MLP, W1L + (LL)l*DIM*MLP, DIM, MLP);
        tconv_k<<<dim3(MLP/32, DIM/32), dim3(32,8), 0, sW>>>(
            W2 + (LL)l*MLP*DIM, W2L + (LL)l*MLP*DIM, MLP, DIM);
        cudaEventRecord(evL[l], sW);
    }

    // ================= main stream =================
    im2col_half<<<(PROWS*DIM + 255)/256, 256>>>(x, Xp);
    cudaStreamWaitEvent(0, evPatch, 0);
    mms<EPI_BIAS, false><<<dim3(6, 49, 1), 256, MS_SMEM>>>(
        Xp, Wp, PO, nullptr, bpatch, nullptr,
        PROWS, DIM, DIM, DIM, DIM, DIM, DIM,
        1, 0, 0, 0, 0, 0, 0, 1.f);
    assemble_k<<<(ROWS*DIM + 255)/256, 256>>>(PO, cls, pos, H);

    for (int l = 0; l < NLAYER; l++) {
        const fp16* Wqkv_l = WqkvL + (LL)l*3*HDK*DIM;
        const float* Bf_l  = BfL + (LL)l*HDK3;
        const fp16* Wo_l   = WoL + (LL)l*HDK*DIM;
        const fp16* W1_l   = W1L + (LL)l*DIM*MLP;
        const fp16* W2_l   = W2L + (LL)l*MLP*DIM;
        const float* bo_l  = bo  + (LL)l*DIM;
        const float* g2_l  = ln2g + (LL)l*DIM;
        const float* b2_l  = ln2b + (LL)l*DIM;
        const float* b1_l  = b1m + (LL)l*MLP;
        const float* bb2_l = b2m + (LL)l*DIM;

        ln_half_k<false><<<ROWS, 256>>>(H, nullptr, nullptr, Xn);

        cudaStreamWaitEvent(0, evL[l], 0);

        mm1<EPI_BIAS|EPI_SPLITH><<<dim3(HDK3/256, 25, 1), 512, MM_SMEM>>>(
            Xn, Wqkv_l, nullptr, QKV, Bf_l, nullptr,
            ROWS, HDK3, HDK3, DIM, DIM, DIM, HDK3, 1.f);

        // scores = Q·K^T / sqrt(768)
        mms<0, false><<<dim3(2, 4, NBH), 256, MS_SMEM>>>(
            QKV, QKV + HDK, S, nullptr, nullptr, nullptr,
            SEQ, SEQ, SEQ, DIM,
            HDK3, HDK3, SEQP,
            NH, (LL)SEQ*HDK3, (LL)DIM, (LL)SEQ*HDK3, (LL)DIM,
            (LL)NH*SEQ*SEQP, (LL)SEQ*SEQP, inv_scale);

        softmax_half_k<<<dim3(NBH, 2), 128>>>(S, Ph);

        // av = P·V (trans-B) -> cat layout
        mms<EPI_SPLITH, true><<<dim3(6, 4, NBH), 256, MS_SMEM>>>(
            Ph, QKV + 2*HDK, nullptr, Cat, nullptr, nullptr,
            SEQ, DIM, SEQ, SEQP,
            SEQP, HDK3, HDK,
            NH, (LL)NH*SEQ*SEQP, (LL)SEQ*SEQP, (LL)SEQ*HDK3, (LL)DIM,
            (LL)SEQ*HDK, (LL)DIM, 1.f);

        // out proj + bias + residual -> H
        mms<EPI_BIAS|EPI_RES, false><<<dim3(6, 50, 1), 256, MS_SMEM>>>(
            Cat, Wo_l, H, nullptr, bo_l, H,
            ROWS, DIM, DIM, HDK, HDK, HDK, DIM,
            1, 0, 0, 0, 0, 0, 0, 1.f);

        // MLP
        ln_half_k<true><<<ROWS, 256>>>(H, g2_l, b2_l, Xn);
        mm1<EPI_BIAS|EPI_GELU|EPI_SPLITH><<<dim3(MLP/256, 25, 1), 512, MM_SMEM>>>(
            Xn, W1_l, nullptr, Hid, b1_l, nullptr,
            ROWS, MLP, MLP, DIM, DIM, DIM, MLP, 1.f);

        mms<EPI_BIAS|EPI_RES, false><<<dim3(6, 50, 1), 256, MS_SMEM>>>(
            Hid, W2_l, H, nullptr, bb2_l, H,
            ROWS, DIM, DIM, MLP, MLP, MLP, DIM,
            1, 0, 0, 0, 0, 0, 0, 1.f);
    }

    // ---- final LN on CLS + classifier ----
    final_head_k<<<BATCH, 256>>>(H, lnfg, lnfb, Wc, bc, out);
}